// round 2
// baseline (speedup 1.0000x reference)
#include <cuda_runtime.h>
#include <cuda_bf16.h>
#include <cstddef>

// Problem constants
#define NTOK   65536          // B*S = 8*8192
#define DMODEL 512
#define HID    2048
#define NEXP   8
#define CHUNK  4096           // tokens per expert slice -> expert = (row>>12)&7

typedef unsigned long long ull;

// ---------------- scratch (static device globals; no allocation) ------------
__device__ float g_norm [(size_t)NTOK * DMODEL];           // 134 MB
__device__ float g_xattn[(size_t)NTOK * DMODEL];           // 134 MB
__device__ float g_h    [(size_t)NTOK * HID];              // 536 MB
__device__ float g_y    [(size_t)NTOK * DMODEL];           // 134 MB

// ---------------- helpers ---------------------------------------------------
__device__ __forceinline__ ull dup2(float v) {
    ull r; asm("mov.b64 %0, {%1, %1};" : "=l"(r) : "f"(v)); return r;
}
__device__ __forceinline__ void fma2(ull& d, ull a, ull b) {
    asm("fma.rn.f32x2 %0, %1, %2, %0;" : "+l"(d) : "l"(a), "l"(b));
}
__device__ __forceinline__ float2 unpack2(ull v) {
    float2 f; asm("mov.b64 {%0, %1}, %2;" : "=f"(f.x), "=f"(f.y) : "l"(v)); return f;
}
__device__ __forceinline__ float gelu_erf(float x) {
    return 0.5f * x * (1.0f + erff(x * 0.70710678118654752f));
}

// ---------------- LayerNorm (warp per token) --------------------------------
__global__ void __launch_bounds__(256) ln_kernel(
    const float* __restrict__ x, const float* __restrict__ g,
    const float* __restrict__ b, float* __restrict__ out)
{
    const int warp = threadIdx.x >> 5;
    const int lane = threadIdx.x & 31;
    const int token = blockIdx.x * 8 + warp;
    const float* row = x + (size_t)token * DMODEL;

    float4 v[4];
    float s = 0.f, ss = 0.f;
#pragma unroll
    for (int q = 0; q < 4; q++) {
        v[q] = *(const float4*)(row + (size_t)(q * 32 + lane) * 4);
        s  += v[q].x + v[q].y + v[q].z + v[q].w;
        ss  = fmaf(v[q].x, v[q].x, ss);
        ss  = fmaf(v[q].y, v[q].y, ss);
        ss  = fmaf(v[q].z, v[q].z, ss);
        ss  = fmaf(v[q].w, v[q].w, ss);
    }
#pragma unroll
    for (int off = 16; off > 0; off >>= 1) {
        s  += __shfl_xor_sync(0xffffffffu, s,  off);
        ss += __shfl_xor_sync(0xffffffffu, ss, off);
    }
    const float mu  = s * (1.0f / DMODEL);
    const float var = ss * (1.0f / DMODEL) - mu * mu;
    const float rs  = rsqrtf(var + 1e-5f);

    float* orow = out + (size_t)token * DMODEL;
#pragma unroll
    for (int q = 0; q < 4; q++) {
        const int c = (q * 32 + lane) * 4;
        float4 gg = *(const float4*)(g + c);
        float4 bb = *(const float4*)(b + c);
        float4 o;
        o.x = (v[q].x - mu) * rs * gg.x + bb.x;
        o.y = (v[q].y - mu) * rs * gg.y + bb.y;
        o.z = (v[q].z - mu) * rs * gg.z + bb.z;
        o.w = (v[q].w - mu) * rs * gg.w + bb.w;
        *(float4*)(orow + c) = o;
    }
}

// ---------------- GEMM: C[r,c] = sum_k A[r,k]*W[e][c,k] + bias (+resid)(gelu)
// BM=BN=128, BK=16, 256 threads, thread tile 8x8 via f32x2 (row-pairs x 8 cols)
template<bool GELU, bool RESID>
__global__ void __launch_bounds__(256) gemm_kernel(
    const float* __restrict__ A, const float* __restrict__ W,
    const float* __restrict__ bias, const float* __restrict__ resid,
    float* __restrict__ C, int K, int OUTD,
    size_t w_estride, int b_estride)
{
    __shared__ __align__(16) float As[16][128];
    __shared__ __align__(16) float Bs[16][128];

    const int tid  = threadIdx.x;
    const int tx   = tid & 15;
    const int ty   = tid >> 4;
    const int row0 = blockIdx.y * 128;
    const int col0 = blockIdx.x * 128;

    const int e = (row0 >> 12) & 7;          // expert id (chunk = 4096 tokens)
    const float* Wp = W + (w_estride ? (size_t)e * w_estride : 0);
    const float* Bp = bias + (b_estride ? e * b_estride : 0);

    ull acc[4][8];
#pragma unroll
    for (int p = 0; p < 4; p++)
#pragma unroll
        for (int j = 0; j < 8; j++) acc[p][j] = 0ull;

    for (int k0 = 0; k0 < K; k0 += 16) {
#pragma unroll
        for (int s = 0; s < 2; s++) {
            const int idx = tid * 2 + s;     // 0..511
            const int r   = idx >> 2;        // 0..127
            const int kk  = (idx & 3) << 2;  // 0,4,8,12
            float4 va = *(const float4*)(A  + (size_t)(row0 + r) * K + (k0 + kk));
            As[kk + 0][r] = va.x; As[kk + 1][r] = va.y;
            As[kk + 2][r] = va.z; As[kk + 3][r] = va.w;
            float4 vb = *(const float4*)(Wp + (size_t)(col0 + r) * K + (k0 + kk));
            Bs[kk + 0][r] = vb.x; Bs[kk + 1][r] = vb.y;
            Bs[kk + 2][r] = vb.z; Bs[kk + 3][r] = vb.w;
        }
        __syncthreads();
#pragma unroll
        for (int k = 0; k < 16; k++) {
            ulonglong2 a0 = *(const ulonglong2*)&As[k][ty * 4];
            ulonglong2 a1 = *(const ulonglong2*)&As[k][64 + ty * 4];
            float4 b0 = *(const float4*)&Bs[k][tx * 4];
            float4 b1 = *(const float4*)&Bs[k][64 + tx * 4];
            ull ap[4] = { a0.x, a0.y, a1.x, a1.y };
            ull bd[8] = { dup2(b0.x), dup2(b0.y), dup2(b0.z), dup2(b0.w),
                          dup2(b1.x), dup2(b1.y), dup2(b1.z), dup2(b1.w) };
#pragma unroll
            for (int p = 0; p < 4; p++)
#pragma unroll
                for (int j = 0; j < 8; j++)
                    fma2(acc[p][j], ap[p], bd[j]);
        }
        __syncthreads();
    }

    // epilogue
#pragma unroll
    for (int p = 0; p < 4; p++) {
        const int rbase = row0 + ((p < 2) ? (ty * 4 + 2 * p)
                                          : (64 + ty * 4 + 2 * (p - 2)));
        float v0[8], v1[8];
#pragma unroll
        for (int j = 0; j < 8; j++) {
            float2 u = unpack2(acc[p][j]);
            v0[j] = u.x; v1[j] = u.y;
        }
#pragma unroll
        for (int h = 0; h < 2; h++) {
            const int r = rbase + h;
            const float* vv = h ? v1 : v0;
#pragma unroll
            for (int g = 0; g < 2; g++) {
                const int c = col0 + (g == 0 ? tx * 4 : 64 + tx * 4);
                float4 bb = *(const float4*)(Bp + c);
                float4 o;
                o.x = vv[g * 4 + 0] + bb.x;
                o.y = vv[g * 4 + 1] + bb.y;
                o.z = vv[g * 4 + 2] + bb.z;
                o.w = vv[g * 4 + 3] + bb.w;
                if (RESID) {
                    float4 rr = *(const float4*)(resid + (size_t)r * OUTD + c);
                    o.x += rr.x; o.y += rr.y; o.z += rr.z; o.w += rr.w;
                }
                if (GELU) {
                    o.x = gelu_erf(o.x); o.y = gelu_erf(o.y);
                    o.z = gelu_erf(o.z); o.w = gelu_erf(o.w);
                }
                *(float4*)(C + (size_t)r * OUTD + c) = o;
            }
        }
    }
}

// ---------------- launch ----------------------------------------------------
extern "C" void kernel_launch(void* const* d_in, const int* in_sizes, int n_in,
                              void* d_out, int out_size)
{
    const float* x      = (const float*)d_in[0];
    const float* ln_g   = (const float*)d_in[1];
    const float* ln_b   = (const float*)d_in[2];
    const float* attn_w = (const float*)d_in[3];
    const float* attn_b = (const float*)d_in[4];
    /* gate_w d_in[5] unused — gating does not affect the output path */
    const float* fc1_w  = (const float*)d_in[6];
    const float* fc1_b  = (const float*)d_in[7];
    const float* fc2_w  = (const float*)d_in[8];
    const float* fc2_b  = (const float*)d_in[9];
    const float* next_w = (const float*)d_in[10];
    const float* next_b = (const float*)d_in[11];
    float* out = (float*)d_out;

    void *p_norm, *p_xattn, *p_h, *p_y;
    cudaGetSymbolAddress(&p_norm,  g_norm);
    cudaGetSymbolAddress(&p_xattn, g_xattn);
    cudaGetSymbolAddress(&p_h,     g_h);
    cudaGetSymbolAddress(&p_y,     g_y);
    float* norm  = (float*)p_norm;
    float* xattn = (float*)p_xattn;
    float* hbuf  = (float*)p_h;
    float* ybuf  = (float*)p_y;

    // 1) LayerNorm
    ln_kernel<<<NTOK / 8, 256>>>(x, ln_g, ln_b, norm);

    // 2) attn linear + residual: xattn = norm @ attn_w^T + attn_b + x
    gemm_kernel<false, true><<<dim3(DMODEL / 128, NTOK / 128), 256>>>(
        norm, attn_w, attn_b, x, xattn, DMODEL, DMODEL, 0, 0);

    // 3) fc1 + gelu (per-expert weights): h = gelu(xattn @ fc1_w[e]^T + fc1_b[e])
    gemm_kernel<true, false><<<dim3(HID / 128, NTOK / 128), 256>>>(
        xattn, fc1_w, fc1_b, nullptr, hbuf, DMODEL, HID,
        (size_t)HID * DMODEL, HID);

    // 4) fc2: y = h @ fc2_w[e]^T + fc2_b[e]
    gemm_kernel<false, false><<<dim3(DMODEL / 128, NTOK / 128), 256>>>(
        hbuf, fc2_w, fc2_b, nullptr, ybuf, HID, DMODEL,
        (size_t)DMODEL * HID, DMODEL);

    // 5) next linear + gelu: out = gelu(y @ next_w^T + next_b)
    gemm_kernel<true, false><<<dim3(DMODEL / 128, NTOK / 128), 256>>>(
        ybuf, next_w, next_b, nullptr, out, DMODEL, DMODEL, 0, 0);
}